// round 15
// baseline (speedup 1.0000x reference)
#include <cuda_runtime.h>
#include <cstdint>

// Problem constants
#define H      2048
#define W      2048
#define FC_IN  1024
#define FC_OUT 10
#define NROWS  4096          // flat rows = H*W/FC_IN

// RNN pipeline config
#define NBLK   32            // pipeline stages (blocks), 64 rows each
#define CH     16            // columns per chunk
#define NCH    256           // chunks; NCH*CH = 4096 (cols 0..4094 used, 4095 pad)
#define NCSK   4096          // padded skewed width

// Static device scratch (no allocation allowed)
__device__ float g_inp[(size_t)NCSK * H];     // inp_cm[c][r] = w*x+b, 32 MB
__device__ float g_uns[(size_t)H * W];        // UNSKEWED activations, row-major, 16 MB
__device__ float g_bnd[NBLK][NCSK + 64];      // boundary-row stream per block
__device__ int   g_flag[NBLK];                // chunk progress (count of published chunks)

// Acquire probe pairs with writer's st.release.gpu (proven R4/R7..R13).
static __device__ __forceinline__ int ld_acq_i(const int* p) {
    int v; asm volatile("ld.acquire.gpu.global.s32 %0, [%1];" : "=r"(v) : "l"(p)); return v;
}
static __device__ __forceinline__ float ld_cg_f(const float* p) {
    float v; asm volatile("ld.global.cg.f32 %0, [%1];" : "=f"(v) : "l"(p)); return v;
}
static __device__ __forceinline__ void st_rel_i(int* p, int v) {
    asm volatile("st.release.gpu.global.s32 [%0], %1;" :: "l"(p), "r"(v) : "memory");
}

// Hardware tanh: single MUFU.TANH. Measured final rel_err 2.86e-6 (R12/R13).
static __device__ __forceinline__ float tanh_hw(float y) {
    float r; asm("tanh.approx.f32 %0, %1;" : "=f"(r) : "f"(y));
    return r;
}

// ---------------------------------------------------------------------------
// Kernel 1: skew + input affine, row-major x -> skewed-column-major g_inp.
// inp_cm[c][r] = w * (0 <= c-r < W ? x[r][c-r] : 0) + b.
// Also resets pipeline flags (stream-ordered before rnn_kernel each replay).
// ---------------------------------------------------------------------------
__global__ void __launch_bounds__(256) skew_kernel(
    const float* __restrict__ x,
    const float* __restrict__ w_in, const float* __restrict__ b_in,
    const float* __restrict__ b_state)
{
    __shared__ float xs[32][66];   // pitch 66 -> diagonal smem reads conflict-free

    if (blockIdx.x == 0 && blockIdx.y == 0) {
        int t = threadIdx.y * 32 + threadIdx.x;
        if (t < NBLK) g_flag[t] = 0;
    }

    const float wL = w_in[0];
    const float cL = b_state[0] + b_in[0];

    const int c0 = blockIdx.x * 32;           // skewed-column tile base
    const int r0 = blockIdx.y * 32;           // row tile base
    const int xb = c0 - r0 - 31;              // x-column window base

    for (int rr = threadIdx.y; rr < 32; rr += 8) {
        const float* xrow = x + (size_t)(r0 + rr) * W;
        #pragma unroll
        for (int tt = 0; tt < 2; tt++) {
            int t = threadIdx.x + tt * 32;
            int xc = xb + t;
            xs[rr][t] = ((unsigned)xc < W) ? xrow[xc] : 0.0f;
        }
    }
    __syncthreads();

    for (int cc = threadIdx.y; cc < 32; cc += 8) {
        int rr = threadIdx.x;
        float v = xs[rr][cc - rr + 31];       // = x[r][(c0+cc)-(r0+rr)] or 0
        g_inp[(size_t)(c0 + cc) * H + (r0 + rr)] = fmaf(wL, v, cL);
    }
}

// ---------------------------------------------------------------------------
// Kernel 2: diagonal-wavefront RNN, warp-specialized, 4-DEEP input ring.
// 32 blocks x 3 warps; block b owns rows [64b, 64b+64); lane -> rows 2l, 2l+1.
//
// w1 producer: register-double-buffered. At iter k: STS chunk k+3 from regs
//              LDG'd at iter k-1 (scoreboard long clean), then fire-and-forget
//              LDG chunk k+4 + acquire-poll flag >= k+5. NEVER waits on a
//              same-iter load -> pure issue (~150 cy), latency fully hidden.
// w0 compute:  pure chain, reads ring slot k&3. Unchanged from R13.
// w2 consumer: one chunk behind; writes UNSKEWED row-major g_uns directly;
//              lane 31 publishes boundary row + release-stores flag=k.
// Inter-block lag grows to ~5 chunks (jitter cushion); steady rate unchanged.
// ---------------------------------------------------------------------------
__global__ void __launch_bounds__(96, 1) rnn_kernel(const float* __restrict__ w_state)
{
    __shared__ float2 sin2[4][CH][32];   // staged inputs, 4-deep ring, 16 KB
    __shared__ float2 sact[2][CH][32];   // staged results, 2-deep, 8 KB
    __shared__ float  sbnd[4][CH];       // staged boundary, 4-deep ring

    const int blk  = blockIdx.x;
    const int wid  = threadIdx.x >> 5;
    const int lane = threadIdx.x & 31;
    const int HP   = H / 2;              // float2 rows per column

    if (wid == 1) {
        // ================= INPUT PRODUCER =================
        const float2* __restrict__ inp2 = ((const float2*)g_inp) + (blk * 32 + lane);
        const int*   fptr = (blk > 0) ? &g_flag[blk - 1] : &g_flag[0];
        const float* bptr = (blk > 0) ? g_bnd[blk - 1]   : g_bnd[0];

        float2 rin[CH];
        float  rb = 0.0f;

        // Prologue: fill ring slots 0..2 (chunks 0..2), preload regs = chunk 3.
        // Chunk f's boundary needs pred flag >= f+1 (cols .. f*CH+CH-2).
        #pragma unroll
        for (int f = 0; f < 3; f++) {
            #pragma unroll
            for (int j = 0; j < CH; j++)
                rin[j] = inp2[(size_t)(f * CH + j) * HP];
            float bv = 0.0f;
            if (lane < CH && blk > 0) {
                int fp; do { fp = ld_acq_i(fptr); } while (fp < f + 1);
                int bi = f * CH - 1 + lane;
                if (bi >= 0) bv = ld_cg_f(bptr + bi);   // f=0,lane=0 -> h[-1]=0
            }
            #pragma unroll
            for (int j = 0; j < CH; j++) sin2[f][j][lane] = rin[j];
            if (lane < CH) sbnd[f][lane] = bv;
        }
        #pragma unroll
        for (int j = 0; j < CH; j++)
            rin[j] = inp2[(size_t)(3 * CH + j) * HP];
        if (lane < CH && blk > 0) {
            int fp; do { fp = ld_acq_i(fptr); } while (fp < 4);
            rb = ld_cg_f(bptr + (3 * CH - 1 + lane));
        }
        __syncthreads();   // ring slots 0..2 ready

        for (int k = 0; k < NCH; k++) {
            const int fs = k + 3;              // chunk to STS (regs from iter k-1)
            if (fs < NCH) {
                #pragma unroll
                for (int j = 0; j < CH; j++) sin2[fs & 3][j][lane] = rin[j];
                if (lane < CH) sbnd[fs & 3][lane] = rb;
                const int fl = k + 4;          // chunk to LDG (consumed iter k+4)
                if (fl < NCH) {
                    #pragma unroll
                    for (int j = 0; j < CH; j++)
                        rin[j] = inp2[(size_t)(fl * CH + j) * HP];
                    if (lane < CH) {
                        rb = 0.0f;
                        if (blk > 0) {
                            int fp; do { fp = ld_acq_i(fptr); } while (fp < fl + 1);
                            rb = ld_cg_f(bptr + (fl * CH - 1 + lane));
                        }
                    }
                }
            }
            __syncthreads();
        }
    } else if (wid == 0) {
        // ================= COMPUTE WARP (no global ops) =================
        const float k0 = w_state[0];   // only 2 tiny const LDGs, prologue
        const float k1 = w_state[1];

        float h0 = 0.0f, h1 = 0.0f;
        __syncthreads();   // ring slots 0..2 ready

        for (int k = 0; k < NCH; k++) {
            const int cb = k & 3;      // input ring slot
            const int ab = k & 1;      // result slot

            float2 pin[CH];
            float  bc[CH];
            #pragma unroll
            for (int j = 0; j < CH; j++) pin[j] = sin2[cb][j][lane];   // LDS.64
            #pragma unroll
            for (int j = 0; j < CH; j++) bc[j]  = sbnd[cb][j];         // broadcast LDS

            #pragma unroll
            for (int j = 0; j < CH; j++) {
                float xn = __shfl_up_sync(0xffffffffu, h1, 1);  // old h[r-1], lanes>0
                if (lane == 0) xn = bc[j];                      // SEL, boundary reg
                float t0 = fmaf(k1, h0, pin[j].x);              // off shfl path
                float t1 = fmaf(k1, h1, pin[j].y);
                float z0 = fmaf(k0, xn, t0);
                float z1 = fmaf(k0, h0, t1);                    // uses OLD h0
                h0 = tanh_hw(z0);                               // MUFU.TANH
                h1 = tanh_hw(z1);
                sact[ab][j][lane] = make_float2(h0, h1);        // STS.64
            }
            __syncthreads();
        }
    } else {
        // ================= OUTPUT CONSUMER (one chunk behind) =================
        // Lane owns rows R0 = 64*blk + 2*lane (even) and R1 = R0+1 (odd).
        // unskewed[r][c - r]: for a chunk, 16 consecutive elements per row.
        const int R0 = blk * 64 + 2 * lane;
        const int R1 = R0 + 1;
        float* __restrict__ row0 = g_uns + (size_t)R0 * W;
        float* __restrict__ row1 = g_uns + (size_t)R1 * W;
        const bool haspub = (blk < NBLK - 1);
        const bool l31    = (lane == 31);

        __syncthreads();   // prologue barrier

        for (int k = 0; k <= NCH; k++) {
            if (k > 0) {
                const int pb  = (k - 1) & 1;
                const int c0p = (k - 1) * CH;
                float2 v[CH];
                #pragma unroll
                for (int j = 0; j < CH; j++) v[j] = sact[pb][j][lane];

                // Even row: base e0 = c0p - R0 is even -> aligned float2 pairs.
                const int e0 = c0p - R0;
                #pragma unroll
                for (int t = 0; t < CH / 2; t++) {
                    int e = e0 + 2 * t;
                    if ((unsigned)e < W)
                        *(float2*)(row0 + e) = make_float2(v[2 * t].x, v[2 * t + 1].x);
                }
                // Odd row: odd base -> scalar stores.
                const int e1 = c0p - R1;
                #pragma unroll
                for (int j = 0; j < CH; j++) {
                    int e = e1 + j;
                    if ((unsigned)e < W) row1[e] = v[j].y;
                }

                if (l31 && haspub) {
                    #pragma unroll
                    for (int j = 0; j < CH; j++) g_bnd[blk][c0p + j] = v[j].y;
                    st_rel_i(&g_flag[blk], k);   // chunks 0..k-1 published
                }
            }
            if (k < NCH) __syncthreads();
            // k == NCH is the tail drain: sact was written before the compute
            // warp's final barrier, so reading it here is race-free.
        }
    }
}

// ---------------------------------------------------------------------------
// Kernel 3: FC, fully coalesced. g_uns row-major flattened IS flat[4096][1024].
// Warp per output row, weights in smem.
// ---------------------------------------------------------------------------
__global__ void __launch_bounds__(256) fc_kernel(
    const float* __restrict__ fcw, const float* __restrict__ fcb,
    float* __restrict__ out)
{
    __shared__ float ws[FC_OUT * FC_IN];   // 40 KB
    int tid = threadIdx.x;
    for (int i = tid; i < FC_OUT * FC_IN; i += 256) ws[i] = fcw[i];
    __syncthreads();

    int warp = tid >> 5, lane = tid & 31;
    int i = blockIdx.x * 8 + warp;         // flat row 0..4095
    const float* xr = g_uns + (size_t)i * FC_IN;

    float xv[32];
    #pragma unroll
    for (int m = 0; m < 32; m++) xv[m] = xr[lane + 32 * m];   // coalesced

    #pragma unroll
    for (int j = 0; j < FC_OUT; j++) {
        float s = 0.0f;
        #pragma unroll
        for (int m = 0; m < 32; m++)
            s = fmaf(xv[m], ws[j * FC_IN + lane + 32 * m], s);
        #pragma unroll
        for (int o = 16; o > 0; o >>= 1)
            s += __shfl_xor_sync(0xffffffffu, s, o);
        if (lane == 0) out[i * FC_OUT + j] = s + fcb[j];
    }
}

extern "C" void kernel_launch(void* const* d_in, const int* in_sizes, int n_in,
                              void* d_out, int out_size)
{
    const float* x       = (const float*)d_in[0];  // [1, 2048, 2048]
    const float* w_in    = (const float*)d_in[1];  // [1,1,1,1]
    const float* b_in    = (const float*)d_in[2];  // [1]
    const float* w_state = (const float*)d_in[3];  // [1,1,2]
    const float* b_state = (const float*)d_in[4];  // [1]
    const float* fc_w    = (const float*)d_in[5];  // [10, 1024]
    const float* fc_b    = (const float*)d_in[6];  // [10]
    float* out = (float*)d_out;                    // [4096, 10]

    // Stream-ordered: skew (also resets flags) -> rnn -> fc. Graph-capturable.
    skew_kernel<<<dim3(NCSK / 32, H / 32), dim3(32, 8)>>>(x, w_in, b_in, b_state);
    // 32 blocks <= 148 SMs: whole pipeline co-resident in wave 1, spins safe.
    rnn_kernel<<<NBLK, 96>>>(w_state);
    fc_kernel<<<NROWS / 8, 256>>>(fc_w, fc_b, out);
}

// round 16
// speedup vs baseline: 1.5502x; 1.5502x over previous
#include <cuda_runtime.h>
#include <cstdint>

// Problem constants
#define H      2048
#define W      2048
#define FC_IN  1024
#define FC_OUT 10
#define NROWS  4096          // flat rows = H*W/FC_IN

// RNN pipeline config
#define NBLK   32            // pipeline stages (blocks), 64 rows each
#define CH     32            // columns per chunk (was 16: halve per-chunk overhead)
#define NCH    128           // chunks; NCH*CH = 4096 (cols 0..4094 used, 4095 pad)
#define NCSK   4096          // padded skewed width

// Static device scratch (no allocation allowed)
__device__ float g_inp[(size_t)NCSK * H];     // inp_cm[c][r] = w*x+b, 32 MB
__device__ float g_uns[(size_t)H * W];        // UNSKEWED activations, row-major, 16 MB
__device__ float g_bnd[NBLK][NCSK + 64];      // boundary-row stream per block
__device__ int   g_flag[NBLK];                // chunk progress (count of published chunks)

// Acquire probe pairs with writer's st.release.gpu (proven R4/R7..R13).
static __device__ __forceinline__ int ld_acq_i(const int* p) {
    int v; asm volatile("ld.acquire.gpu.global.s32 %0, [%1];" : "=r"(v) : "l"(p)); return v;
}
static __device__ __forceinline__ float ld_cg_f(const float* p) {
    float v; asm volatile("ld.global.cg.f32 %0, [%1];" : "=f"(v) : "l"(p)); return v;
}
static __device__ __forceinline__ void st_rel_i(int* p, int v) {
    asm volatile("st.release.gpu.global.s32 [%0], %1;" :: "l"(p), "r"(v) : "memory");
}

// Hardware tanh: single MUFU.TANH. Measured final rel_err 2.86e-6 (R12/R13).
static __device__ __forceinline__ float tanh_hw(float y) {
    float r; asm("tanh.approx.f32 %0, %1;" : "=f"(r) : "f"(y));
    return r;
}

// ---------------------------------------------------------------------------
// Kernel 1: skew + input affine, row-major x -> skewed-column-major g_inp.
// inp_cm[c][r] = w * (0 <= c-r < W ? x[r][c-r] : 0) + b.
// Also resets pipeline flags (stream-ordered before rnn_kernel each replay).
// ---------------------------------------------------------------------------
__global__ void __launch_bounds__(256) skew_kernel(
    const float* __restrict__ x,
    const float* __restrict__ w_in, const float* __restrict__ b_in,
    const float* __restrict__ b_state)
{
    __shared__ float xs[32][66];   // pitch 66 -> diagonal smem reads conflict-free

    if (blockIdx.x == 0 && blockIdx.y == 0) {
        int t = threadIdx.y * 32 + threadIdx.x;
        if (t < NBLK) g_flag[t] = 0;
    }

    const float wL = w_in[0];
    const float cL = b_state[0] + b_in[0];

    const int c0 = blockIdx.x * 32;           // skewed-column tile base
    const int r0 = blockIdx.y * 32;           // row tile base
    const int xb = c0 - r0 - 31;              // x-column window base

    for (int rr = threadIdx.y; rr < 32; rr += 8) {
        const float* xrow = x + (size_t)(r0 + rr) * W;
        #pragma unroll
        for (int tt = 0; tt < 2; tt++) {
            int t = threadIdx.x + tt * 32;
            int xc = xb + t;
            xs[rr][t] = ((unsigned)xc < W) ? xrow[xc] : 0.0f;
        }
    }
    __syncthreads();

    for (int cc = threadIdx.y; cc < 32; cc += 8) {
        int rr = threadIdx.x;
        float v = xs[rr][cc - rr + 31];       // = x[r][(c0+cc)-(r0+rr)] or 0
        g_inp[(size_t)(c0 + cc) * H + (r0 + rr)] = fmaf(wL, v, cL);
    }
}

// ---------------------------------------------------------------------------
// Kernel 2: diagonal-wavefront RNN, warp-specialized (R13 structure, CH=32).
// 32 blocks x 3 warps; block b owns rows [64b, 64b+64); lane -> rows 2l, 2l+1.
//
// w1 producer: stages chunk k+1 during iter k (LDG->smem, acquire-poll pred
//              flag >= k+2, boundary -> smem). Proven R13 dataflow.
// w0 compute:  pure chain + NEW: lane 31 publishes the boundary row (STG) and
//              release-stores flag = k+1 at END of chunk k. Cuts inter-block
//              lag from 2 chunks to ~1 and gives producers a chunk of slack.
//              (Own-thread store->release ordering, protocol proven R4..R13.)
// w2 consumer: one chunk behind; writes UNSKEWED row-major g_uns only.
// ---------------------------------------------------------------------------
__global__ void __launch_bounds__(96, 1) rnn_kernel(const float* __restrict__ w_state)
{
    __shared__ float2 sin2[2][CH][32];   // staged inputs  [buf][col][lane], 16 KB
    __shared__ float2 sact[2][CH][32];   // staged results [buf][col][lane], 16 KB
    __shared__ float  sbnd[2][CH];       // staged boundary [buf][col]

    const int blk  = blockIdx.x;
    const int wid  = threadIdx.x >> 5;
    const int lane = threadIdx.x & 31;
    const int HP   = H / 2;              // float2 rows per column

    if (wid == 1) {
        // ================= INPUT PRODUCER =================
        const float2* __restrict__ inp2 = ((const float2*)g_inp) + (blk * 32 + lane);
        const int*   fptr = (blk > 0) ? &g_flag[blk - 1] : &g_flag[0];
        const float* bptr = (blk > 0) ? g_bnd[blk - 1]   : g_bnd[0];

        // Prologue: stage chunk 0 (inputs + boundary cols -1..CH-2; col -1 -> 0)
        #pragma unroll
        for (int j = 0; j < CH; j++)
            sin2[0][j][lane] = inp2[(size_t)j * HP];
        {
            float b0 = 0.0f;
            if (blk > 0) {
                int fp; do { fp = ld_acq_i(fptr); } while (fp < 1);
                if (lane > 0) b0 = ld_cg_f(bptr + (lane - 1));
                if (lane >= CH) b0 = 0.0f;     // only first CH slots used (CH==32: all)
            }
            if (lane < CH) sbnd[0][lane] = b0;
        }
        __syncthreads();

        for (int k = 0; k < NCH; k++) {
            if (k + 1 < NCH) {
                const int nb = (k + 1) & 1;
                const int cn = (k + 1) * CH;
                #pragma unroll
                for (int j = 0; j < CH; j++)
                    sin2[nb][j][lane] = inp2[(size_t)(cn + j) * HP];
                if (lane < CH) {
                    float bv = 0.0f;
                    if (blk > 0) {
                        const int tgt = k + 2;   // cols up to (k+2)*CH-2 needed
                        int fp; do { fp = ld_acq_i(fptr); } while (fp < tgt);
                        bv = ld_cg_f(bptr + (cn - 1 + lane));
                    }
                    sbnd[nb][lane] = bv;
                }
            }
            __syncthreads();
        }
    } else if (wid == 0) {
        // ================= COMPUTE WARP =================
        const float k0 = w_state[0];   // only 2 tiny const LDGs, prologue
        const float k1 = w_state[1];
        const bool haspub = (blk < NBLK - 1);
        const bool l31    = (lane == 31);

        float h0 = 0.0f, h1 = 0.0f;
        __syncthreads();   // buffer 0 ready

        for (int k = 0; k < NCH; k++) {
            const int cb = k & 1;
            const int c0 = k * CH;

            float2 pin[CH];
            float  bc[CH];
            #pragma unroll
            for (int j = 0; j < CH; j++) pin[j] = sin2[cb][j][lane];   // LDS.64
            #pragma unroll
            for (int j = 0; j < CH; j++) bc[j]  = sbnd[cb][j];         // broadcast LDS

            #pragma unroll
            for (int j = 0; j < CH; j++) {
                float xn = __shfl_up_sync(0xffffffffu, h1, 1);  // old h[r-1], lanes>0
                if (lane == 0) xn = bc[j];                      // SEL, boundary reg
                float t0 = fmaf(k1, h0, pin[j].x);              // off shfl path
                float t1 = fmaf(k1, h1, pin[j].y);
                float z0 = fmaf(k0, xn, t0);
                float z1 = fmaf(k0, h0, t1);                    // uses OLD h0
                h0 = tanh_hw(z0);                               // MUFU.TANH
                h1 = tanh_hw(z1);
                sact[cb][j][lane] = make_float2(h0, h1);        // STS.64
                if (l31 && haspub) g_bnd[blk][c0 + j] = h1;     // bottom-row stream
            }
            // Publish chunk k immediately (one chunk earlier than R13's
            // consumer publish): release orders lane 31's own g_bnd stores.
            if (l31 && haspub) st_rel_i(&g_flag[blk], k + 1);

            __syncthreads();
        }
    } else {
        // ================= OUTPUT CONSUMER (one chunk behind) =================
        // Lane owns rows R0 = 64*blk + 2*lane (even) and R1 = R0+1 (odd).
        // unskewed[r][c - r]: for a chunk, CH consecutive elements per row.
        const int R0 = blk * 64 + 2 * lane;
        const int R1 = R0 + 1;
        float* __restrict__ row0 = g_uns + (size_t)R0 * W;
        float* __restrict__ row1 = g_uns + (size_t)R1 * W;

        __syncthreads();   // prologue barrier

        for (int k = 0; k <= NCH; k++) {
            if (k > 0) {
                const int pb  = (k - 1) & 1;
                const int c0p = (k - 1) * CH;
                float2 v[CH];
                #pragma unroll
                for (int j = 0; j < CH; j++) v[j] = sact[pb][j][lane];

                // Even row: base e0 = c0p - R0 is even -> aligned float2 pairs.
                const int e0 = c0p - R0;
                #pragma unroll
                for (int t = 0; t < CH / 2; t++) {
                    int e = e0 + 2 * t;
                    if ((unsigned)e < W)
                        *(float2*)(row0 + e) = make_float2(v[2 * t].x, v[2 * t + 1].x);
                }
                // Odd row: odd base -> scalar stores.
                const int e1 = c0p - R1;
                #pragma unroll
                for (int j = 0; j < CH; j++) {
                    int e = e1 + j;
                    if ((unsigned)e < W) row1[e] = v[j].y;
                }
            }
            if (k < NCH) __syncthreads();
            // k == NCH is the tail drain: sact was written before the compute
            // warp's final barrier, so reading it here is race-free.
        }
    }
}

// ---------------------------------------------------------------------------
// Kernel 3: FC, fully coalesced. g_uns row-major flattened IS flat[4096][1024].
// Warp per output row, weights in smem.
// ---------------------------------------------------------------------------
__global__ void __launch_bounds__(256) fc_kernel(
    const float* __restrict__ fcw, const float* __restrict__ fcb,
    float* __restrict__ out)
{
    __shared__ float ws[FC_OUT * FC_IN];   // 40 KB
    int tid = threadIdx.x;
    for (int i = tid; i < FC_OUT * FC_IN; i += 256) ws[i] = fcw[i];
    __syncthreads();

    int warp = tid >> 5, lane = tid & 31;
    int i = blockIdx.x * 8 + warp;         // flat row 0..4095
    const float* xr = g_uns + (size_t)i * FC_IN;

    float xv[32];
    #pragma unroll
    for (int m = 0; m < 32; m++) xv[m] = xr[lane + 32 * m];   // coalesced

    #pragma unroll
    for (int j = 0; j < FC_OUT; j++) {
        float s = 0.0f;
        #pragma unroll
        for (int m = 0; m < 32; m++)
            s = fmaf(xv[m], ws[j * FC_IN + lane + 32 * m], s);
        #pragma unroll
        for (int o = 16; o > 0; o >>= 1)
            s += __shfl_xor_sync(0xffffffffu, s, o);
        if (lane == 0) out[i * FC_OUT + j] = s + fcb[j];
    }
}

extern "C" void kernel_launch(void* const* d_in, const int* in_sizes, int n_in,
                              void* d_out, int out_size)
{
    const float* x       = (const float*)d_in[0];  // [1, 2048, 2048]
    const float* w_in    = (const float*)d_in[1];  // [1,1,1,1]
    const float* b_in    = (const float*)d_in[2];  // [1]
    const float* w_state = (const float*)d_in[3];  // [1,1,2]
    const float* b_state = (const float*)d_in[4];  // [1]
    const float* fc_w    = (const float*)d_in[5];  // [10, 1024]
    const float* fc_b    = (const float*)d_in[6];  // [10]
    float* out = (float*)d_out;                    // [4096, 10]

    // Stream-ordered: skew (also resets flags) -> rnn -> fc. Graph-capturable.
    skew_kernel<<<dim3(NCSK / 32, H / 32), dim3(32, 8)>>>(x, w_in, b_in, b_state);
    // 32 blocks <= 148 SMs: whole pipeline co-resident in wave 1, spins safe.
    rnn_kernel<<<NBLK, 96>>>(w_state);
    fc_kernel<<<NROWS / 8, 256>>>(fc_w, fc_b, out);
}